// round 13
// baseline (speedup 1.0000x reference)
#include <cuda_runtime.h>
#include <math.h>
#include <float.h>

#define N 256
#define NBLK 128              // 2 rows per block, single wave
#define FULL 0xffffffffu

typedef unsigned long long ull;

// packed f32x2 fused multiply-add: acc.lo += a.lo*b.lo; acc.hi += a.hi*b.hi
#define FMA2(acc, a, b) \
    asm("fma.rn.f32x2 %0, %1, %2, %3;" : "=l"(acc) : "l"(a), "l"(b), "l"(acc))

__device__ __forceinline__ float unpack_add(ull v) {
    float lo, hi;
    asm("mov.b64 {%0,%1}, %2;" : "=f"(lo), "=f"(hi) : "l"(v));
    return lo + hi;
}

__device__ float2 g_part[NBLK];
__device__ unsigned int g_ticket = 0;   // reset by last block each launch

// Dynamic smem: full E, 8192 float4 = 128KB, swizzled: row j chunk c at j*32+((c+j)&31)
extern __shared__ float4 sE[];

__global__ void __launch_bounds__(256, 1)
triplet_fused(const float* __restrict__ emb,
              const int*   __restrict__ lab32,
              float*       __restrict__ out) {
    __shared__ float  Dmat[2 * N];
    __shared__ float  negd[2 * N];
    __shared__ unsigned short pairs[2 * N];
    __shared__ int    cnts[16];
    __shared__ float  wsum[8];

    const int t = threadIdx.x;
    const int b = blockIdx.x;
    const int w = t >> 5, l = t & 31;
    const int i0 = b * 2, i1 = i0 + 1;

    // ---- Per-warp staging: warp w stages ITS OWN rows [32w, 32w+32).
    // Per row j, lane l cp.asyncs chunk l (512B contiguous per row, coalesced).
    unsigned sb = (unsigned)__cvta_generic_to_shared(sE);
    const float4* E4 = reinterpret_cast<const float4*>(emb);
    const int jbase = w * 32;
#pragma unroll
    for (int jj = 0; jj < 32; ++jj) {
        const int j = jbase + jj;
        unsigned dst = sb + ((unsigned)((j << 5) + ((l + j) & 31)) << 4);
        asm volatile("cp.async.cg.shared.global [%0], [%1], 16;"
                     :: "r"(dst), "l"(E4 + j * 32 + l));
    }
    asm volatile("cp.async.commit_group;");

    // ---- Warp-local label dtype sniff while copies fly (no barrier, no smem).
    // int64 LE labels (0..15) have all-zero odd 32-bit words; words [0..255]
    // are in-bounds for both layouts.
    unsigned any = 0;
#pragma unroll
    for (int k = 0; k < 4; ++k)
        any |= (unsigned)lab32[2 * (l + 32 * k) + 1];
    const bool is64 = (__ballot_sync(FULL, any != 0) == 0);
    const int labT  = is64 ? lab32[2 * t]  : lab32[t];
    const int labI0 = is64 ? lab32[2 * i0] : lab32[i0];
    const int labI1 = is64 ? lab32[2 * i1] : lab32[i1];

    asm volatile("cp.async.wait_group 0;");
    __syncwarp();   // own warp's rows visible; no block barrier needed

    // ---- Phase 1 (packed f32x2): own row from smem, anchors via uniform LDG.
    // Anchor norms computed redundantly -> no norm exchange, no barrier.
    const ulonglong2* rowp = reinterpret_cast<const ulonglong2*>(sE + (t << 5));
    const ulonglong2* gA = reinterpret_cast<const ulonglong2*>(emb + i0 * 128);
    const ulonglong2* gB = reinterpret_cast<const ulonglong2*>(emb + i1 * 128);
    ull d0p = 0, d0q = 0, d1p = 0, d1q = 0, np = 0, nq = 0;
    ull m0p = 0, m0q = 0, m1p = 0, m1q = 0;
#pragma unroll 8
    for (int c = 0; c < 32; ++c) {
        ulonglong2 bv = rowp[(c + t) & 31];   // conflict-free (swizzle)
        ulonglong2 a0 = __ldg(gA + c);        // uniform -> broadcast, L1-hot
        ulonglong2 a1 = __ldg(gB + c);
        FMA2(d0p, bv.x, a0.x);  FMA2(d0q, bv.y, a0.y);
        FMA2(d1p, bv.x, a1.x);  FMA2(d1q, bv.y, a1.y);
        FMA2(np,  bv.x, bv.x);  FMA2(nq,  bv.y, bv.y);
        FMA2(m0p, a0.x, a0.x);  FMA2(m0q, a0.y, a0.y);
        FMA2(m1p, a1.x, a1.x);  FMA2(m1q, a1.y, a1.y);
    }
    const float dot0 = unpack_add(d0p) + unpack_add(d0q);
    const float dot1 = unpack_add(d1p) + unpack_add(d1q);
    const float nt   = unpack_add(np)  + unpack_add(nq);
    const float an0  = unpack_add(m0p) + unpack_add(m0q);
    const float an1  = unpack_add(m1p) + unpack_add(m1q);

    // ---- Phase 2: distances, masks, per-warp counts.
    const float D0 = sqrtf(fmaxf(an0 + nt - 2.f * dot0, 1e-4f));
    const float D1 = sqrtf(fmaxf(an1 + nt - 2.f * dot1, 1e-4f));
    const bool p0 = (labT == labI0) && (t != i0);
    const bool p1 = (labT == labI1) && (t != i1);
    Dmat[t]     = D0;  Dmat[N + t] = D1;
    // negatives include t==i (reference's (1-pos) keeps diagonal; d_ii=0.01)
    negd[t]     = p0 ? -FLT_MAX : D0;
    negd[N + t] = p1 ? -FLT_MAX : D1;
    const unsigned bal0 = __ballot_sync(FULL, p0);
    const unsigned bal1 = __ballot_sync(FULL, p1);
    if (l == 0) { cnts[w] = __popc(bal0); cnts[8 + w] = __popc(bal1); }
    __syncthreads();   // S1: Dmat/negd/cnts ready

    // ---- In-warp redundant prefix scan of the 16 counts (no extra barrier).
    int x = (l < 16) ? cnts[l] : 0;
    const int v0 = x;
#pragma unroll
    for (int d = 1; d < 16; d <<= 1) {
        int y = __shfl_up_sync(FULL, x, d);
        if (l >= d) x += y;
    }
    const int exc = x - v0;
    const int npair = __shfl_sync(FULL, x, 15);
    const int off0 = __shfl_sync(FULL, exc, w);
    const int off1 = __shfl_sync(FULL, exc, 8 + w);
    const unsigned lm = (1u << l) - 1u;
    if (p0) pairs[off0 + __popc(bal0 & lm)] = (unsigned short)t;
    if (p1) pairs[off1 + __popc(bal1 & lm)] = (unsigned short)(256 | t);
    __syncthreads();   // S2: pairs ready

    // ---- Phase 3: one warp per positive pair.
    float lsum = 0.f;
    for (int p = w; p < npair; p += 8) {
        const unsigned pr = pairs[p];
        const int r = pr >> 8, k = pr & 255;
        const float Dk = Dmat[r * N + k];
        const float* nd = negd + r * N;
        float mx = -FLT_MAX, mn = FLT_MAX;
#pragma unroll
        for (int u = 0; u < 8; ++u) {
            float vv = nd[u * 32 + l];
            mx = fmaxf(mx, vv);
            mn = fminf(mn, vv > Dk ? vv : FLT_MAX);
        }
#pragma unroll
        for (int s = 16; s > 0; s >>= 1) {   // two chains overlap
            mx = fmaxf(mx, __shfl_down_sync(FULL, mx, s));
            mn = fminf(mn, __shfl_down_sync(FULL, mn, s));
        }
        if (l == 0) {
            // semi-hard if strictly-farther negative exists, else easiest neg
            float semi = (mn < FLT_MAX) ? (Dk - mn) : (Dk - mx);
            lsum += fmaxf(semi + 1.0f, 0.f);   // relu(semi + MARGIN)
        }
    }
    if (l == 0) wsum[w] = lsum;
    __syncthreads();   // S3 (last barrier)

    // ---- Ticket + finisher: warp 0 only, no fence, no more barriers.
    if (w == 0) {
        int last = 0;
        if (l == 0) {
            float S = 0.f;
#pragma unroll
            for (int k = 0; k < 8; ++k) S += wsum[k];
            g_part[b] = make_float2(S, (float)npair);
            unsigned tk, one = 1u;
            asm volatile("atom.acq_rel.gpu.global.add.u32 %0, [%1], %2;"
                         : "=r"(tk) : "l"(&g_ticket), "r"(one) : "memory");
            last = (tk == NBLK - 1);
            if (last) g_ticket = 0;   // all increments done; replay-safe
        }
        last = __shfl_sync(FULL, last, 0);
        if (last) {
            float S = 0.f, C = 0.f;
#pragma unroll
            for (int u = 0; u < 4; ++u) {
                float2 p = __ldcg(&g_part[l + 32 * u]);   // L2-direct
                S += p.x; C += p.y;
            }
#pragma unroll
            for (int s = 16; s > 0; s >>= 1) {
                S += __shfl_down_sync(FULL, S, s);
                C += __shfl_down_sync(FULL, C, s);
            }
            if (l == 0) out[0] = S / C;
        }
    }
}

extern "C" void kernel_launch(void* const* d_in, const int* in_sizes, int n_in,
                              void* d_out, int out_size) {
    const float* emb  = (const float*)d_in[0];
    const int*   labs = (const int*)d_in[1];
    float* out = (float*)d_out;
    cudaFuncSetAttribute(triplet_fused,
                         cudaFuncAttributeMaxDynamicSharedMemorySize, 131072);
    triplet_fused<<<NBLK, 256, 131072>>>(emb, labs, out);
}

// round 15
// speedup vs baseline: 1.2143x; 1.2143x over previous
#include <cuda_runtime.h>
#include <math.h>
#include <float.h>

#define N 256
#define NBLK 128              // 2 rows per block, single wave
#define FULL 0xffffffffu

typedef unsigned long long ull;

// packed f32x2 fused multiply-add: acc.lo += a.lo*b.lo; acc.hi += a.hi*b.hi
#define FMA2(acc, a, b) \
    asm("fma.rn.f32x2 %0, %1, %2, %3;" : "=l"(acc) : "l"(a), "l"(b), "l"(acc))

__device__ __forceinline__ float unpack_add(ull v) {
    float lo, hi;
    asm("mov.b64 {%0,%1}, %2;" : "=f"(lo), "=f"(hi) : "l"(v));
    return lo + hi;
}

__device__ float2 g_part[NBLK];
__device__ unsigned int g_ticket = 0;   // reset by last block each launch

// Dynamic smem: full E, 8192 float4 = 128KB, swizzled: row j chunk c at j*32+((c+j)&31)
extern __shared__ float4 sE[];

__global__ void __launch_bounds__(256, 1)
triplet_fused(const float* __restrict__ emb,
              const int*   __restrict__ lab32,
              float*       __restrict__ out) {
    __shared__ float  normsh[N];
    __shared__ float  Dmat[2 * N];
    __shared__ float  negd[2 * N];
    __shared__ unsigned short pairs[2 * N];
    __shared__ int    cnts[16];
    __shared__ float  wsum[8];
    __shared__ int    sh_flag;

    const int t = threadIdx.x;
    const int b = blockIdx.x;
    const int w = t >> 5, l = t & 31;
    const int i0 = b * 2, i1 = i0 + 1;

    // ---- Stage E into smem (plain LDG+STS, swizzled dst) — R11 exact.
    const float4* E4 = reinterpret_cast<const float4*>(emb);
#pragma unroll
    for (int p = 0; p < 32; ++p) {
        const int g = p * 256 + t;
        const int j = g >> 5, c = g & 31;
        sE[(j << 5) + ((c + j) & 31)] = E4[g];
    }

    // ---- Label dtype sniff (warp 0, ballot — no init barrier needed).
    // int64 LE labels (0..15) have all-zero odd 32-bit words; words [0..255]
    // are in-bounds for both layouts.
    if (w == 0) {
        unsigned any = 0;
#pragma unroll
        for (int k = 0; k < 4; ++k)
            any |= (unsigned)lab32[2 * (l + 32 * k) + 1];
        unsigned balz = __ballot_sync(FULL, any != 0);
        if (l == 0) sh_flag = (balz != 0);
    }
    __syncthreads();   // S1: sE + sh_flag ready

    const bool is64 = (sh_flag == 0);
    const int labT  = is64 ? lab32[2 * t]  : lab32[t];
    const int labI0 = is64 ? lab32[2 * i0] : lab32[i0];
    const int labI1 = is64 ? lab32[2 * i1] : lab32[i1];

    // ---- Phase 1 (packed f32x2): own row + anchor broadcasts, all smem.
    // 6 independent accumulator chains (dep distance 6 > lat 4): no stalls.
    const ulonglong2* rowp = reinterpret_cast<const ulonglong2*>(sE + (t  << 5));
    const ulonglong2* rA   = reinterpret_cast<const ulonglong2*>(sE + (i0 << 5));
    const ulonglong2* rB   = reinterpret_cast<const ulonglong2*>(sE + (i1 << 5));
    ull d0x = 0, d0y = 0, d1x = 0, d1y = 0, nx = 0, ny = 0;
#pragma unroll 8
    for (int c = 0; c < 32; ++c) {
        ulonglong2 bv = rowp[(c + t)  & 31];   // conflict-free (swizzle)
        ulonglong2 a0 = rA[(c + i0) & 31];     // uniform addr -> broadcast
        ulonglong2 a1 = rB[(c + i1) & 31];
        FMA2(d0x, bv.x, a0.x);  FMA2(d0y, bv.y, a0.y);
        FMA2(d1x, bv.x, a1.x);  FMA2(d1y, bv.y, a1.y);
        FMA2(nx,  bv.x, bv.x);  FMA2(ny,  bv.y, bv.y);
    }
    const float dot0 = unpack_add(d0x) + unpack_add(d0y);
    const float dot1 = unpack_add(d1x) + unpack_add(d1y);
    const float nt   = unpack_add(nx)  + unpack_add(ny);
    normsh[t] = nt;
    __syncthreads();   // S2: anchor norms visible

    // ---- Phase 2: distances, masks, per-warp counts.
    const float D0 = sqrtf(fmaxf(normsh[i0] + nt - 2.f * dot0, 1e-4f));
    const float D1 = sqrtf(fmaxf(normsh[i1] + nt - 2.f * dot1, 1e-4f));
    const bool p0 = (labT == labI0) && (t != i0);
    const bool p1 = (labT == labI1) && (t != i1);
    Dmat[t]     = D0;  Dmat[N + t] = D1;
    // negatives include t==i (reference's (1-pos) keeps diagonal; d_ii=0.01)
    negd[t]     = p0 ? -FLT_MAX : D0;
    negd[N + t] = p1 ? -FLT_MAX : D1;
    const unsigned bal0 = __ballot_sync(FULL, p0);
    const unsigned bal1 = __ballot_sync(FULL, p1);
    if (l == 0) { cnts[w] = __popc(bal0); cnts[8 + w] = __popc(bal1); }
    __syncthreads();   // S3: Dmat/negd/cnts ready

    // ---- In-warp redundant prefix scan of the 16 counts (no extra barrier).
    int x = (l < 16) ? cnts[l] : 0;
    const int v0 = x;
#pragma unroll
    for (int d = 1; d < 16; d <<= 1) {
        int y = __shfl_up_sync(FULL, x, d);
        if (l >= d) x += y;
    }
    const int exc = x - v0;                     // exclusive offset at slot l
    const int npair = __shfl_sync(FULL, x, 15); // total positives (uniform)
    const int off0 = __shfl_sync(FULL, exc, w);      // slot w     (r=0)
    const int off1 = __shfl_sync(FULL, exc, 8 + w);  // slot 8+w   (r=1)
    const unsigned lm = (1u << l) - 1u;
    if (p0) pairs[off0 + __popc(bal0 & lm)] = (unsigned short)t;
    if (p1) pairs[off1 + __popc(bal1 & lm)] = (unsigned short)(256 | t);
    __syncthreads();   // S4: pairs ready

    // ---- Phase 3: one warp per positive pair.
    float lsum = 0.f;
    for (int p = w; p < npair; p += 8) {
        const unsigned pr = pairs[p];
        const int r = pr >> 8, k = pr & 255;
        const float Dk = Dmat[r * N + k];
        const float* nd = negd + r * N;
        float mx = -FLT_MAX, mn = FLT_MAX;
#pragma unroll
        for (int u = 0; u < 8; ++u) {
            float vv = nd[u * 32 + l];
            mx = fmaxf(mx, vv);
            mn = fminf(mn, vv > Dk ? vv : FLT_MAX);
        }
#pragma unroll
        for (int s = 16; s > 0; s >>= 1) {   // two chains overlap
            mx = fmaxf(mx, __shfl_down_sync(FULL, mx, s));
            mn = fminf(mn, __shfl_down_sync(FULL, mn, s));
        }
        if (l == 0) {
            // semi-hard if strictly-farther negative exists, else easiest neg
            float semi = (mn < FLT_MAX) ? (Dk - mn) : (Dk - mx);
            lsum += fmaxf(semi + 1.0f, 0.f);   // relu(semi + MARGIN)
        }
    }
    if (l == 0) wsum[w] = lsum;
    __syncthreads();   // S5 (last barrier)

    // ---- Ticket + finisher: warp 0 only, no fence, no more barriers.
    if (w == 0) {
        int last = 0;
        if (l == 0) {
            float S = 0.f;
#pragma unroll
            for (int k = 0; k < 8; ++k) S += wsum[k];
            g_part[b] = make_float2(S, (float)npair);
            unsigned tk, one = 1u;
            asm volatile("atom.acq_rel.gpu.global.add.u32 %0, [%1], %2;"
                         : "=r"(tk) : "l"(&g_ticket), "r"(one) : "memory");
            last = (tk == NBLK - 1);
            if (last) g_ticket = 0;   // all increments done; replay-safe
        }
        last = __shfl_sync(FULL, last, 0);
        if (last) {
            float S = 0.f, C = 0.f;
#pragma unroll
            for (int u = 0; u < 4; ++u) {
                float2 p = __ldcg(&g_part[l + 32 * u]);   // L2-direct
                S += p.x; C += p.y;
            }
#pragma unroll
            for (int s = 16; s > 0; s >>= 1) {
                S += __shfl_down_sync(FULL, S, s);
                C += __shfl_down_sync(FULL, C, s);
            }
            if (l == 0) out[0] = S / C;
        }
    }
}

extern "C" void kernel_launch(void* const* d_in, const int* in_sizes, int n_in,
                              void* d_out, int out_size) {
    const float* emb  = (const float*)d_in[0];
    const int*   labs = (const int*)d_in[1];
    float* out = (float*)d_out;
    cudaFuncSetAttribute(triplet_fused,
                         cudaFuncAttributeMaxDynamicSharedMemorySize, 131072);
    triplet_fused<<<NBLK, 256, 131072>>>(emb, labs, out);
}